// round 3
// baseline (speedup 1.0000x reference)
#include <cuda_runtime.h>
#include <cuda_bf16.h>
#include <cstdint>

// Problem constants (fixed by the dataset)
#define N_NODES 100000
#define N_EDGES 1600000
#define N_FEAT  128
#define HIDDEN  64
#define N_OUT   10
#define N_GRAPHS 64

#define SCAN_B 1024
#define N_SCAN_BLOCKS ((N_NODES + SCAN_B - 1) / SCAN_B)   // 98

// ---------------- device scratch (static, no allocation) ----------------
__device__ int    g_deg[N_NODES];          // degree incl. self loop
__device__ float  g_dis[N_NODES];          // rsqrt(deg)
__device__ int    g_rowptr[N_NODES + 1];   // CSR offsets (edges only)
__device__ int    g_cursor[N_NODES];       // fill cursors
__device__ int    g_scan_tmp[N_NODES];     // per-block exclusive scan
__device__ int    g_bsum[N_SCAN_BLOCKS];   // block sums -> block offsets
__device__ __align__(16) int2  g_csr_pack[N_EDGES];              // (src, norm-as-bits)
__device__ __align__(16) float g_tmpA[(size_t)N_NODES * HIDDEN]; // h @ W
__device__ __align__(16) float g_tmpB[(size_t)N_NODES * HIDDEN]; // aggregated h
__device__ float  g_pool_sums[N_GRAPHS * HIDDEN];
__device__ float  g_pool_cnt[N_GRAPHS];

// ---------------- init: deg=1 (self loop), zero pool accumulators -------
__global__ void init_kernel() {
    int i = blockIdx.x * blockDim.x + threadIdx.x;
    if (i < N_NODES) g_deg[i] = 1;
    if (i < N_GRAPHS * HIDDEN) g_pool_sums[i] = 0.f;
    if (i < N_GRAPHS) g_pool_cnt[i] = 0.f;
}

// ---------------- degree histogram over targets (col) -------------------
__global__ void count_kernel(const int* __restrict__ ei) {
    int e = blockIdx.x * blockDim.x + threadIdx.x;
    if (e < N_EDGES) {
        int c = ei[e + N_EDGES];   // col / target
        atomicAdd(&g_deg[c], 1);
    }
}

__global__ void dis_kernel() {
    int i = blockIdx.x * blockDim.x + threadIdx.x;
    if (i < N_NODES) g_dis[i] = rsqrtf((float)g_deg[i]);
}

// ---------------- exclusive scan of (deg-1) over 100K nodes -------------
__global__ void scan1_kernel() {
    __shared__ int s[SCAN_B];
    int tid = threadIdx.x;
    int i = blockIdx.x * SCAN_B + tid;
    int v = (i < N_NODES) ? (g_deg[i] - 1) : 0;
    s[tid] = v;
    __syncthreads();
    #pragma unroll
    for (int off = 1; off < SCAN_B; off <<= 1) {
        int t = (tid >= off) ? s[tid - off] : 0;
        __syncthreads();
        s[tid] += t;
        __syncthreads();
    }
    if (i < N_NODES) g_scan_tmp[i] = s[tid] - v;   // exclusive
    if (tid == SCAN_B - 1) g_bsum[blockIdx.x] = s[tid];
}

__global__ void scan2_kernel() {
    // single thread: tiny (98 entries)
    int run = 0;
    for (int b = 0; b < N_SCAN_BLOCKS; b++) {
        int t = g_bsum[b];
        g_bsum[b] = run;
        run += t;
    }
    g_rowptr[N_NODES] = run;   // == N_EDGES
}

__global__ void scan3_kernel() {
    int i = blockIdx.x * SCAN_B + threadIdx.x;
    if (i < N_NODES) {
        int v = g_scan_tmp[i] + g_bsum[blockIdx.x];
        g_rowptr[i] = v;
        g_cursor[i] = v;
    }
}

// ---------------- CSR fill with precomputed norm -------------------------
__global__ void fill_kernel(const int* __restrict__ ei) {
    int e = blockIdx.x * blockDim.x + threadIdx.x;
    if (e < N_EDGES) {
        int r = ei[e];
        int c = ei[e + N_EDGES];
        int pos = atomicAdd(&g_cursor[c], 1);
        float nr = g_dis[r] * g_dis[c];
        g_csr_pack[pos] = make_int2(r, __float_as_int(nr));
    }
}

// ---------------- SGEMM: g_tmpA[M,64] = A[M,K] @ W[K,64] -----------------
// A = x (sel==0) or g_tmpB (sel==1). 64x64 tile, 256 threads, 4x4 microtile.
template <int K>
__global__ __launch_bounds__(256)
void gemm_kernel(const float* __restrict__ x, const float* __restrict__ W,
                 int sel, int M) {
    __shared__ float Ws[K * 64];
    __shared__ float As[32 * 64];   // [k][m]

    const float* __restrict__ A = (sel == 0) ? x : (const float*)g_tmpB;
    float* __restrict__ C = g_tmpA;

    const int tid = threadIdx.x;
    const int tx = tid & 15;    // 0..15 -> cols tx*4..+3
    const int ty = tid >> 4;    // 0..15 -> rows ty*4..+3
    const int row0 = blockIdx.x * 64;

    for (int i = tid; i < K * 64; i += 256) Ws[i] = W[i];

    float acc[4][4] = {};

    for (int kk = 0; kk < K; kk += 32) {
        __syncthreads();
        // load A tile [64 rows][32 k] transposed into As[k][m]
        #pragma unroll
        for (int p = 0; p < 2; p++) {
            int slot = tid + p * 256;    // 0..511
            int r = slot >> 3;           // 0..63
            int q = slot & 7;            // 0..7 (float4 along K)
            int grow = row0 + r;
            float4 v = make_float4(0.f, 0.f, 0.f, 0.f);
            if (grow < M)
                v = *(const float4*)(A + (size_t)grow * K + kk + q * 4);
            As[(q * 4 + 0) * 64 + r] = v.x;
            As[(q * 4 + 1) * 64 + r] = v.y;
            As[(q * 4 + 2) * 64 + r] = v.z;
            As[(q * 4 + 3) * 64 + r] = v.w;
        }
        __syncthreads();
        #pragma unroll
        for (int k = 0; k < 32; k++) {
            float4 a = *(const float4*)(As + k * 64 + ty * 4);
            float4 b = *(const float4*)(Ws + (kk + k) * 64 + tx * 4);
            acc[0][0] += a.x * b.x; acc[0][1] += a.x * b.y; acc[0][2] += a.x * b.z; acc[0][3] += a.x * b.w;
            acc[1][0] += a.y * b.x; acc[1][1] += a.y * b.y; acc[1][2] += a.y * b.z; acc[1][3] += a.y * b.w;
            acc[2][0] += a.z * b.x; acc[2][1] += a.z * b.y; acc[2][2] += a.z * b.z; acc[2][3] += a.z * b.w;
            acc[3][0] += a.w * b.x; acc[3][1] += a.w * b.y; acc[3][2] += a.w * b.z; acc[3][3] += a.w * b.w;
        }
    }

    #pragma unroll
    for (int i = 0; i < 4; i++) {
        int r = row0 + ty * 4 + i;
        if (r < M)
            *(float4*)(C + (size_t)r * 64 + tx * 4) =
                make_float4(acc[i][0], acc[i][1], acc[i][2], acc[i][3]);
    }
}

// ---------------- aggregation: g_tmpB[i] = sum_in(g_tmpA[src]*norm)
//                               + g_tmpA[i]/deg + b, optional relu
// one warp per node; lane owns 2 consecutive features (float2)
__global__ void aggregate_kernel(const float* __restrict__ bias, int relu) {
    int warp = (blockIdx.x * blockDim.x + threadIdx.x) >> 5;
    if (warp >= N_NODES) return;
    int lane = threadIdx.x & 31;

    const float* __restrict__ hW = g_tmpA;
    float* __restrict__ out = g_tmpB;

    int start = g_rowptr[warp];
    int end   = g_rowptr[warp + 1];
    float d = g_dis[warp];
    float w = d * d;   // self loop weight = 1/deg

    float2 s = *(const float2*)(hW + (size_t)warp * 64 + lane * 2);
    float ax = s.x * w, ay = s.y * w;

    for (int k = start; k < end; k++) {
        int2 p = g_csr_pack[k];
        float nr = __int_as_float(p.y);
        float2 v = *(const float2*)(hW + (size_t)p.x * 64 + lane * 2);
        ax += v.x * nr;
        ay += v.y * nr;
    }

    ax += bias[lane * 2];
    ay += bias[lane * 2 + 1];
    if (relu) { ax = fmaxf(ax, 0.f); ay = fmaxf(ay, 0.f); }
    *(float2*)(out + (size_t)warp * 64 + lane * 2) = make_float2(ax, ay);
}

// ---------------- mean pool over sorted batch ----------------------------
// block = 256 threads = 4 slots x 64 cols; slot handles 128 contiguous nodes
__global__ void pool_kernel(const int* __restrict__ batch) {
    const float* __restrict__ h = g_tmpB;
    int col  = threadIdx.x & 63;
    int slot = threadIdx.x >> 6;
    int n0 = blockIdx.x * 512 + slot * 128;
    if (n0 >= N_NODES) return;
    int n1 = min(n0 + 128, N_NODES);

    float acc = 0.f, cnt = 0.f;
    int cur = batch[n0];
    for (int i = n0; i < n1; i++) {
        int g = batch[i];
        if (g != cur) {
            atomicAdd(&g_pool_sums[cur * 64 + col], acc);
            if (col == 0) atomicAdd(&g_pool_cnt[cur], cnt);
            cur = g; acc = 0.f; cnt = 0.f;
        }
        acc += h[(size_t)i * 64 + col];
        cnt += 1.f;
    }
    atomicAdd(&g_pool_sums[cur * 64 + col], acc);
    if (col == 0) atomicAdd(&g_pool_cnt[cur], cnt);
}

// ---------------- final linear: out = (sums/cnt) @ Wlin + blin ----------
__global__ void final_kernel(const float* __restrict__ Wlin,
                             const float* __restrict__ blin,
                             float* __restrict__ out) {
    int tid = threadIdx.x;
    if (tid >= N_GRAPHS * N_OUT) return;
    int g = tid / N_OUT;
    int o = tid % N_OUT;
    float inv = 1.f / fmaxf(g_pool_cnt[g], 1.f);
    float acc = blin[o];
    #pragma unroll
    for (int c = 0; c < 64; c++)
        acc += g_pool_sums[g * 64 + c] * inv * Wlin[c * N_OUT + o];
    out[g * N_OUT + o] = acc;
}

// ---------------- launch ------------------------------------------------
extern "C" void kernel_launch(void* const* d_in, const int* in_sizes, int n_in,
                              void* d_out, int out_size) {
    const float* x    = (const float*)d_in[0];
    const int*   ei   = (const int*)d_in[1];     // int32 (JAX default x64-disabled)
    const int*   batch= (const int*)d_in[2];     // int32
    const float* W1   = (const float*)d_in[3];
    const float* b1   = (const float*)d_in[4];
    const float* W2   = (const float*)d_in[5];
    const float* b2   = (const float*)d_in[6];
    const float* W3   = (const float*)d_in[7];
    const float* b3   = (const float*)d_in[8];
    const float* Wlin = (const float*)d_in[9];
    const float* blin = (const float*)d_in[10];
    float* out = (float*)d_out;

    const int EBLK = (N_EDGES + 255) / 256;
    const int NBLK = (N_NODES + 255) / 256;

    // graph normalization + CSR build
    init_kernel<<<NBLK, 256>>>();
    count_kernel<<<EBLK, 256>>>(ei);
    dis_kernel<<<NBLK, 256>>>();
    scan1_kernel<<<N_SCAN_BLOCKS, SCAN_B>>>();
    scan2_kernel<<<1, 1>>>();
    scan3_kernel<<<N_SCAN_BLOCKS, SCAN_B>>>();
    fill_kernel<<<EBLK, 256>>>(ei);

    const int GEMM_BLK = (N_NODES + 63) / 64;
    const int AGG_BLK  = (N_NODES * 32 + 255) / 256;

    // layer 1
    gemm_kernel<128><<<GEMM_BLK, 256>>>(x, W1, 0, N_NODES);
    aggregate_kernel<<<AGG_BLK, 256>>>(b1, 1);
    // layer 2
    gemm_kernel<64><<<GEMM_BLK, 256>>>(x, W2, 1, N_NODES);
    aggregate_kernel<<<AGG_BLK, 256>>>(b2, 1);
    // layer 3
    gemm_kernel<64><<<GEMM_BLK, 256>>>(x, W3, 1, N_NODES);
    aggregate_kernel<<<AGG_BLK, 256>>>(b3, 0);

    // pool + head
    pool_kernel<<<(N_NODES + 511) / 512, 256>>>(batch);
    final_kernel<<<1, N_GRAPHS * N_OUT>>>(Wlin, blin, out);
}